// round 15
// baseline (speedup 1.0000x reference)
#include <cuda_runtime.h>

// DCT band decomposition: x[16,3,512,512] f32 -> (low, mid, high) concatenated.
// One thread per 8x8 block. Butterfly forward DCT; band IDCTs exploit
// m/(7-m) and n/(7-n) cosine symmetry; DCT constants fold to FFMA immediates.
// Blackwell 256-bit global loads/stores (v8.f32): one instruction per 32B
// row chunk, fully-written sectors. launch_bounds(128,6) = measured optimum.
// Stores use default write-back policy (L2 absorbs bursts; .cs measured
// suspect for forcing early DRAM drain).

namespace {
constexpr int H = 512, W = 512;
constexpr int NPIX = 16 * 3 * H * W;             // 12582912
constexpr int NBLK = 16 * 3 * (H / 8) * (W / 8); // 196608
constexpr int TPB  = 128;
}

#define A4f 0.3535533905932738f
#define C1f 0.4903926402016152f
#define C2f 0.4619397662556434f
#define C3f 0.4157348061512726f
#define C5f 0.2777851165098011f
#define C6f 0.1913417161825449f
#define C7f 0.0975451610080641f

__host__ __device__ constexpr float Dv(int k, int t) {
    constexpr float m[8][8] = {
        { A4f,  A4f,  A4f,  A4f,  A4f,  A4f,  A4f,  A4f},
        { C1f,  C3f,  C5f,  C7f, -C7f, -C5f, -C3f, -C1f},
        { C2f,  C6f, -C6f, -C2f, -C2f, -C6f,  C6f,  C2f},
        { C3f, -C7f, -C1f, -C5f,  C5f,  C1f,  C7f, -C3f},
        { A4f, -A4f, -A4f,  A4f,  A4f, -A4f, -A4f,  A4f},
        { C5f, -C1f,  C7f,  C3f, -C3f, -C7f,  C1f, -C5f},
        { C6f, -C2f,  C2f, -C6f, -C6f,  C2f, -C2f,  C6f},
        { C7f, -C5f,  C3f, -C1f,  C1f, -C3f,  C5f, -C7f}
    };
    return m[k][t];
}

// Zigzag bands: low = zz<21 <=> k+l<=5 ; mid = 21<=zz<42 <=> 6<=k+l<=8 \ (1,7)
__host__ __device__ constexpr bool in_band(int band, int k, int l) {
    const int s = k + l;
    const bool low = (s <= 5);
    const bool mid = (s >= 6 && s <= 8) && !(k == 1 && l == 7);
    if (band == 0) return low;
    if (band == 1) return mid;
    return !low && !mid;
}
__host__ __device__ constexpr bool col_active(int band, int l) {
    bool a = false;
    for (int k = 0; k < 8; k++) if (in_band(band, k, l)) a = true;
    return a;
}

// ---- 256-bit global memory ops (sm_100a/sm_103a) ----
__device__ __forceinline__ void ldg256(const float* p, float v[8]) {
    asm("ld.global.nc.v8.f32 {%0,%1,%2,%3,%4,%5,%6,%7}, [%8];"
        : "=f"(v[0]), "=f"(v[1]), "=f"(v[2]), "=f"(v[3]),
          "=f"(v[4]), "=f"(v[5]), "=f"(v[6]), "=f"(v[7])
        : "l"(p));
}
__device__ __forceinline__ void stg256(float* p, const float v[8]) {
    asm volatile("st.global.v8.f32 [%0], {%1,%2,%3,%4,%5,%6,%7,%8};"
                 :: "l"(p),
                    "f"(v[0]), "f"(v[1]), "f"(v[2]), "f"(v[3]),
                    "f"(v[4]), "f"(v[5]), "f"(v[6]), "f"(v[7])
                 : "memory");
}

// Fast 8-point DCT-II (orthonormal) in place.
__device__ __forceinline__ void dct8(float x[8]) {
    const float e0 = x[0] + x[7], e1 = x[1] + x[6], e2 = x[2] + x[5], e3 = x[3] + x[4];
    const float o0 = x[0] - x[7], o1 = x[1] - x[6], o2 = x[2] - x[5], o3 = x[3] - x[4];
    const float f0 = e0 + e3, f1 = e1 + e2;
    const float g0 = e0 - e3, g1 = e1 - e2;
    x[0] = A4f * (f0 + f1);
    x[4] = A4f * (f0 - f1);
    x[2] = fmaf(C2f, g0,  C6f * g1);
    x[6] = fmaf(C6f, g0, -C2f * g1);
    x[1] = fmaf(C1f, o0, fmaf( C3f, o1, fmaf( C5f, o2,  C7f * o3)));
    x[3] = fmaf(C3f, o0, fmaf(-C7f, o1, fmaf(-C1f, o2, -C5f * o3)));
    x[5] = fmaf(C5f, o0, fmaf(-C1f, o1, fmaf( C7f, o2,  C3f * o3)));
    x[7] = fmaf(C7f, o0, fmaf(-C5f, o1, fmaf( C3f, o2, -C1f * o3)));
}

// Stage 2 of masked IDCT: o[n] = sum_l y[l]*Dv(l,n) with n/(7-n) symmetry.
template <int BAND>
__device__ __forceinline__ void idct_row_store(const float y[8],
                                               float* __restrict__ dst)
{
    float o[8];
#pragma unroll
    for (int n = 0; n < 4; n++) {
        float E = 0.0f, O = 0.0f;
#pragma unroll
        for (int l = 0; l < 8; l += 2)
            if (col_active(BAND, l)) E = fmaf(y[l], Dv(l, n), E);
#pragma unroll
        for (int l = 1; l < 8; l += 2)
            if (col_active(BAND, l)) O = fmaf(y[l], Dv(l, n), O);
        o[n]     = E + O;
        o[7 - n] = E - O;
    }
    stg256(dst, o);
}

// Masked inverse DCT of one band, row pairs (m, 7-m):
// Dv(k,7-m) = (-1)^k Dv(k,m), so stage-1 even/odd-k partial sums are shared.
template <int BAND>
__device__ __forceinline__ void band_idct(const float C[8][8], float scale,
                                          float* __restrict__ dst)
{
#pragma unroll
    for (int m = 0; m < 4; m++) {
        float yA[8], yB[8];
#pragma unroll
        for (int l = 0; l < 8; l++) {
            if (col_active(BAND, l)) {
                float se = 0.0f, so = 0.0f;
#pragma unroll
                for (int k = 0; k < 8; k += 2)
                    if (in_band(BAND, k, l)) se = fmaf(C[k][l], Dv(k, m), se);
#pragma unroll
                for (int k = 1; k < 8; k += 2)
                    if (in_band(BAND, k, l)) so = fmaf(C[k][l], Dv(k, m), so);
                yA[l] = (se + so) * scale;   // row m
                yB[l] = (se - so) * scale;   // row 7-m
            } else {
                yA[l] = 0.0f; yB[l] = 0.0f;
            }
        }
        idct_row_store<BAND>(yA, dst + (size_t)m * W);
        idct_row_store<BAND>(yB, dst + (size_t)(7 - m) * W);
    }
}

__global__ void __launch_bounds__(TPB, 6)
dct_decomp_kernel(const float* __restrict__ x,
                  const float* __restrict__ band_scale,
                  float* __restrict__ out)
{
    const int tid = blockIdx.x * TPB + threadIdx.x;   // grid sized exactly
    const int bw = tid & 63;          // block col (W/8 = 64)
    const int bh = (tid >> 6) & 63;   // block row
    const int bc = tid >> 12;         // fused batch*chan

    const size_t base = ((size_t)bc * H + (size_t)bh * 8) * W + (size_t)bw * 8;
    const float* src = x + base;

    const float s0 = __ldg(band_scale + 0);
    const float s1 = __ldg(band_scale + 1);
    const float s2 = __ldg(band_scale + 2);

    // ---- Load 8x8 block: 8 independent 256-bit loads, front-batched ----
    float C[8][8];
#pragma unroll
    for (int r = 0; r < 8; r++)
        ldg256(src + (size_t)r * W, C[r]);

    // ---- Forward 2D DCT in place: columns then rows, butterflied ----
#pragma unroll
    for (int t = 0; t < 8; t++) {
        float col[8];
#pragma unroll
        for (int m = 0; m < 8; m++) col[m] = C[m][t];
        dct8(col);
#pragma unroll
        for (int k = 0; k < 8; k++) C[k][t] = col[k];
    }
#pragma unroll
    for (int k = 0; k < 8; k++)
        dct8(C[k]);

    // ---- Three masked inverse DCTs ----
    band_idct<0>(C, s0, out + base);
    band_idct<1>(C, s1, out + (size_t)NPIX + base);
    band_idct<2>(C, s2, out + 2 * (size_t)NPIX + base);
}

extern "C" void kernel_launch(void* const* d_in, const int* in_sizes, int n_in,
                              void* d_out, int out_size)
{
    const float* x  = (const float*)d_in[0];
    const float* bs = (const float*)d_in[1];
    float* out = (float*)d_out;

    const int grid = NBLK / TPB;   // 1536
    dct_decomp_kernel<<<grid, TPB>>>(x, bs, out);
}

// round 16
// speedup vs baseline: 1.0133x; 1.0133x over previous
#include <cuda_runtime.h>

// DCT band decomposition: x[16,3,512,512] f32 -> (low, mid, high) concatenated.
// One thread per 8x8 block. Butterfly forward DCT; band IDCTs exploit
// m/(7-m) and n/(7-n) cosine symmetry; DCT constants fold to FFMA immediates.
// Blackwell 256-bit global loads/stores (v8.f32). TPB=64 x 12 CTAs/SM: same
// 24 warps/SM and same 80-reg binary as the 128x6 optimum, but half the
// per-CTA duration -> half the end-of-kernel drain tail, finer wave balance.

namespace {
constexpr int H = 512, W = 512;
constexpr int NPIX = 16 * 3 * H * W;             // 12582912
constexpr int NBLK = 16 * 3 * (H / 8) * (W / 8); // 196608
constexpr int TPB  = 64;
}

#define A4f 0.3535533905932738f
#define C1f 0.4903926402016152f
#define C2f 0.4619397662556434f
#define C3f 0.4157348061512726f
#define C5f 0.2777851165098011f
#define C6f 0.1913417161825449f
#define C7f 0.0975451610080641f

__host__ __device__ constexpr float Dv(int k, int t) {
    constexpr float m[8][8] = {
        { A4f,  A4f,  A4f,  A4f,  A4f,  A4f,  A4f,  A4f},
        { C1f,  C3f,  C5f,  C7f, -C7f, -C5f, -C3f, -C1f},
        { C2f,  C6f, -C6f, -C2f, -C2f, -C6f,  C6f,  C2f},
        { C3f, -C7f, -C1f, -C5f,  C5f,  C1f,  C7f, -C3f},
        { A4f, -A4f, -A4f,  A4f,  A4f, -A4f, -A4f,  A4f},
        { C5f, -C1f,  C7f,  C3f, -C3f, -C7f,  C1f, -C5f},
        { C6f, -C2f,  C2f, -C6f, -C6f,  C2f, -C2f,  C6f},
        { C7f, -C5f,  C3f, -C1f,  C1f, -C3f,  C5f, -C7f}
    };
    return m[k][t];
}

// Zigzag bands: low = zz<21 <=> k+l<=5 ; mid = 21<=zz<42 <=> 6<=k+l<=8 \ (1,7)
__host__ __device__ constexpr bool in_band(int band, int k, int l) {
    const int s = k + l;
    const bool low = (s <= 5);
    const bool mid = (s >= 6 && s <= 8) && !(k == 1 && l == 7);
    if (band == 0) return low;
    if (band == 1) return mid;
    return !low && !mid;
}
__host__ __device__ constexpr bool col_active(int band, int l) {
    bool a = false;
    for (int k = 0; k < 8; k++) if (in_band(band, k, l)) a = true;
    return a;
}

// ---- 256-bit global memory ops (sm_100a/sm_103a) ----
__device__ __forceinline__ void ldg256(const float* p, float v[8]) {
    asm("ld.global.nc.v8.f32 {%0,%1,%2,%3,%4,%5,%6,%7}, [%8];"
        : "=f"(v[0]), "=f"(v[1]), "=f"(v[2]), "=f"(v[3]),
          "=f"(v[4]), "=f"(v[5]), "=f"(v[6]), "=f"(v[7])
        : "l"(p));
}
__device__ __forceinline__ void stg256_cs(float* p, const float v[8]) {
    asm volatile("st.global.cs.v8.f32 [%0], {%1,%2,%3,%4,%5,%6,%7,%8};"
                 :: "l"(p),
                    "f"(v[0]), "f"(v[1]), "f"(v[2]), "f"(v[3]),
                    "f"(v[4]), "f"(v[5]), "f"(v[6]), "f"(v[7])
                 : "memory");
}

// Fast 8-point DCT-II (orthonormal) in place.
__device__ __forceinline__ void dct8(float x[8]) {
    const float e0 = x[0] + x[7], e1 = x[1] + x[6], e2 = x[2] + x[5], e3 = x[3] + x[4];
    const float o0 = x[0] - x[7], o1 = x[1] - x[6], o2 = x[2] - x[5], o3 = x[3] - x[4];
    const float f0 = e0 + e3, f1 = e1 + e2;
    const float g0 = e0 - e3, g1 = e1 - e2;
    x[0] = A4f * (f0 + f1);
    x[4] = A4f * (f0 - f1);
    x[2] = fmaf(C2f, g0,  C6f * g1);
    x[6] = fmaf(C6f, g0, -C2f * g1);
    x[1] = fmaf(C1f, o0, fmaf( C3f, o1, fmaf( C5f, o2,  C7f * o3)));
    x[3] = fmaf(C3f, o0, fmaf(-C7f, o1, fmaf(-C1f, o2, -C5f * o3)));
    x[5] = fmaf(C5f, o0, fmaf(-C1f, o1, fmaf( C7f, o2,  C3f * o3)));
    x[7] = fmaf(C7f, o0, fmaf(-C5f, o1, fmaf( C3f, o2, -C1f * o3)));
}

// Stage 2 of masked IDCT: o[n] = sum_l y[l]*Dv(l,n) with n/(7-n) symmetry.
template <int BAND>
__device__ __forceinline__ void idct_row_store(const float y[8],
                                               float* __restrict__ dst)
{
    float o[8];
#pragma unroll
    for (int n = 0; n < 4; n++) {
        float E = 0.0f, O = 0.0f;
#pragma unroll
        for (int l = 0; l < 8; l += 2)
            if (col_active(BAND, l)) E = fmaf(y[l], Dv(l, n), E);
#pragma unroll
        for (int l = 1; l < 8; l += 2)
            if (col_active(BAND, l)) O = fmaf(y[l], Dv(l, n), O);
        o[n]     = E + O;
        o[7 - n] = E - O;
    }
    stg256_cs(dst, o);
}

// Masked inverse DCT of one band, row pairs (m, 7-m):
// Dv(k,7-m) = (-1)^k Dv(k,m), so stage-1 even/odd-k partial sums are shared.
template <int BAND>
__device__ __forceinline__ void band_idct(const float C[8][8], float scale,
                                          float* __restrict__ dst)
{
#pragma unroll
    for (int m = 0; m < 4; m++) {
        float yA[8], yB[8];
#pragma unroll
        for (int l = 0; l < 8; l++) {
            if (col_active(BAND, l)) {
                float se = 0.0f, so = 0.0f;
#pragma unroll
                for (int k = 0; k < 8; k += 2)
                    if (in_band(BAND, k, l)) se = fmaf(C[k][l], Dv(k, m), se);
#pragma unroll
                for (int k = 1; k < 8; k += 2)
                    if (in_band(BAND, k, l)) so = fmaf(C[k][l], Dv(k, m), so);
                yA[l] = (se + so) * scale;   // row m
                yB[l] = (se - so) * scale;   // row 7-m
            } else {
                yA[l] = 0.0f; yB[l] = 0.0f;
            }
        }
        idct_row_store<BAND>(yA, dst + (size_t)m * W);
        idct_row_store<BAND>(yB, dst + (size_t)(7 - m) * W);
    }
}

__global__ void __launch_bounds__(TPB, 12)
dct_decomp_kernel(const float* __restrict__ x,
                  const float* __restrict__ band_scale,
                  float* __restrict__ out)
{
    const int tid = blockIdx.x * TPB + threadIdx.x;   // grid sized exactly
    const int bw = tid & 63;          // block col (W/8 = 64)
    const int bh = (tid >> 6) & 63;   // block row
    const int bc = tid >> 12;         // fused batch*chan

    const size_t base = ((size_t)bc * H + (size_t)bh * 8) * W + (size_t)bw * 8;
    const float* src = x + base;

    const float s0 = __ldg(band_scale + 0);
    const float s1 = __ldg(band_scale + 1);
    const float s2 = __ldg(band_scale + 2);

    // ---- Load 8x8 block: 8 independent 256-bit loads, front-batched ----
    float C[8][8];
#pragma unroll
    for (int r = 0; r < 8; r++)
        ldg256(src + (size_t)r * W, C[r]);

    // ---- Forward 2D DCT in place: columns then rows, butterflied ----
#pragma unroll
    for (int t = 0; t < 8; t++) {
        float col[8];
#pragma unroll
        for (int m = 0; m < 8; m++) col[m] = C[m][t];
        dct8(col);
#pragma unroll
        for (int k = 0; k < 8; k++) C[k][t] = col[k];
    }
#pragma unroll
    for (int k = 0; k < 8; k++)
        dct8(C[k]);

    // ---- Three masked inverse DCTs ----
    band_idct<0>(C, s0, out + base);
    band_idct<1>(C, s1, out + (size_t)NPIX + base);
    band_idct<2>(C, s2, out + 2 * (size_t)NPIX + base);
}

extern "C" void kernel_launch(void* const* d_in, const int* in_sizes, int n_in,
                              void* d_out, int out_size)
{
    const float* x  = (const float*)d_in[0];
    const float* bs = (const float*)d_in[1];
    float* out = (float*)d_out;

    const int grid = NBLK / TPB;   // 3072
    dct_decomp_kernel<<<grid, TPB>>>(x, bs, out);
}